// round 1
// baseline (speedup 1.0000x reference)
#include <cuda_runtime.h>
#include <cstdint>

// Problem constants (dataset-fixed): T=2048, N=4096, max_spikes=128.
// Phase A: single-CTA coupled simulation until nsp == max_spikes.
// Phase B: fully parallel per-neuron free dynamics for remaining steps.

#define MAXN 4096
#define NPT 8                 // neurons per thread in phase A
#define BLKA (MAXN / NPT)     // 512 threads

static __device__ float g_sv[MAXN];
static __device__ float g_si[MAXN];
static __device__ float g_ss[MAXN];
static __device__ int   g_tstart;

__device__ __forceinline__ float sigmoid_acc(float x) {
    // 1/(1+exp(-x)) with accurate expf and IEEE divide: stays within ~1-2 ulp
    // of XLA's logistic expansion (0.5 + 0.5*tanh(0.5x)).
    float e = expf(-x);
    float d = __fadd_rn(1.0f, e);
    return 1.0f / d;
}

__device__ __forceinline__ void ld8(const float* __restrict__ p, float* a) {
    float4 x = *(const float4*)(p);
    float4 y = *(const float4*)(p + 4);
    a[0] = x.x; a[1] = x.y; a[2] = x.z; a[3] = x.w;
    a[4] = y.x; a[5] = y.y; a[6] = y.z; a[7] = y.w;
}

// ---------------------------------------------------------------------------
// Phase A: coupled event-driven phase. One CTA; all state in registers.
// Exact-rounding ops in the reference's expression order (no FMA contraction)
// because the s>=0 threshold crossing makes the system chaotic in idx.
// ---------------------------------------------------------------------------
__global__ void __launch_bounds__(BLKA, 1)
snn_phaseA(const float* __restrict__ ts, const float* __restrict__ inp,
           const float* __restrict__ w, const float* __restrict__ v0,
           const float* __restrict__ i0, const float* __restrict__ mu,
           const float* __restrict__ s0u, const float* __restrict__ ru,
           const int* __restrict__ msp, float* __restrict__ out,
           int T, int N)
{
    __shared__ int s_wmin[BLKA / 32];
    __shared__ int s_res;

    const int tid  = threadIdx.x;
    const int base = tid * NPT;
    const float dt   = __fsub_rn(ts[1], ts[0]);
    const float mu1  = mu[0];
    const float mu2  = mu[1];
    const float nmu2 = -mu2;             // reference: dt * (-mu2 * i)
    const int max_spikes = msp[0];

    float v[NPT], ci[NPT], s[NPT];
    ld8(v0 + base, v);
    ld8(i0 + base, ci);
    {
        float u[NPT];
        ld8(s0u + base, u);
        #pragma unroll
        for (int k = 0; k < NPT; ++k)
            s[k] = __fsub_rn(logf(__fadd_rn(u[k], 1e-12f)), 0.01f);
    }

    int nsp = 0;
    int t_end = T;

    float cin[NPT];
    ld8(inp + base, cin);                 // input row for t = 0

    for (int t = 0; t < T; ++t) {
        // Prefetch next input row (clamped index; unused garbage on last step).
        float nin[NPT];
        {
            int tn = t + 1 < T ? t + 1 : T - 1;
            ld8(inp + (size_t)tn * N + base, nin);
        }

        float vn[NPT], in_[NPT], sn[NPT];
        #pragma unroll
        for (int k = 0; k < NPT; ++k) {
            float d1 = __fsub_rn(ci[k], v[k]);
            float a  = __fmul_rn(mu1, d1);
            float b  = __fmul_rn(mu1, cin[k]);
            float c  = __fadd_rn(a, b);
            vn[k]  = __fadd_rn(v[k], __fmul_rn(dt, c));
            in_[k] = __fadd_rn(ci[k], __fmul_rn(dt, __fmul_rn(nmu2, ci[k])));
            float sg = sigmoid_acc(v[k]);      // sigmoid of OLD v
            sn[k] = __fadd_rn(s[k], __fmul_rn(dt, sg));
        }

        // First firing index across the block (argmax over boolean ev).
        unsigned lm = 0x7FFFFFFFu;
        #pragma unroll
        for (int k = NPT - 1; k >= 0; --k)
            if (sn[k] >= 0.0f) lm = (unsigned)(base + k);
        lm = __reduce_min_sync(0xFFFFFFFFu, lm);
        if ((tid & 31) == 0) s_wmin[tid >> 5] = (int)lm;
        __syncthreads();
        if (tid < 32) {
            unsigned m = (tid < (BLKA / 32)) ? (unsigned)s_wmin[tid] : 0x7FFFFFFFu;
            m = __reduce_min_sync(0xFFFFFFFFu, m);
            if (tid == 0) s_res = (int)m;
        }
        __syncthreads();

        const int  idx  = s_res;
        const bool fire = (idx != 0x7FFFFFFF) && (nsp < max_spikes);

        if (fire) {
            float wr[NPT];
            ld8(w + (size_t)idx * N + base, wr);
            const float* __restrict__ rrow = ru + (size_t)t * N + base;
            #pragma unroll
            for (int k = 0; k < NPT; ++k) {
                if (sn[k] >= 0.0f) {
                    vn[k] = __fsub_rn(vn[k], 1.0f);                       // V_RESET
                    sn[k] = __fsub_rn(logf(__fadd_rn(rrow[k], 1e-12f)), 0.01f);
                } else {
                    in_[k] = __fadd_rn(in_[k], wr[k]);
                }
            }
            ++nsp;
        }

        #pragma unroll
        for (int k = 0; k < NPT; ++k) { v[k] = vn[k]; ci[k] = in_[k]; s[k] = sn[k]; }

        // 8 neurons x (v,i,s) = 24 floats = 6 contiguous float4 stores.
        float4* op = (float4*)(out + ((size_t)t * N + base) * 3);
        op[0] = make_float4(v[0], ci[0], s[0], v[1]);
        op[1] = make_float4(ci[1], s[1], v[2], ci[2]);
        op[2] = make_float4(s[2], v[3], ci[3], s[3]);
        op[3] = make_float4(v[4], ci[4], s[4], v[5]);
        op[4] = make_float4(ci[5], s[5], v[6], ci[6]);
        op[5] = make_float4(s[6], v[7], ci[7], s[7]);

        #pragma unroll
        for (int k = 0; k < NPT; ++k) cin[k] = nin[k];

        if (nsp >= max_spikes) { t_end = t + 1; break; }   // uniform across block
    }

    // Persist state for phase B.
    *(float4*)(g_sv + base)     = make_float4(v[0], v[1], v[2], v[3]);
    *(float4*)(g_sv + base + 4) = make_float4(v[4], v[5], v[6], v[7]);
    *(float4*)(g_si + base)     = make_float4(ci[0], ci[1], ci[2], ci[3]);
    *(float4*)(g_si + base + 4) = make_float4(ci[4], ci[5], ci[6], ci[7]);
    *(float4*)(g_ss + base)     = make_float4(s[0], s[1], s[2], s[3]);
    *(float4*)(g_ss + base + 4) = make_float4(s[4], s[5], s[6], s[7]);
    if (tid == 0) g_tstart = t_end;
}

// ---------------------------------------------------------------------------
// Phase B: after nsp == max_spikes, fire is permanently false -> pure
// per-neuron free dynamics. One thread per neuron, 4-deep input prefetch.
// ---------------------------------------------------------------------------
__device__ __forceinline__ void stepB_store(float dt, float mu1, float nmu2,
                                            float in_cur, float& v, float& i, float& s,
                                            float* __restrict__ out, size_t ob)
{
    float d1 = __fsub_rn(i, v);
    float a  = __fmul_rn(mu1, d1);
    float b  = __fmul_rn(mu1, in_cur);
    float c  = __fadd_rn(a, b);
    float sg = sigmoid_acc(v);
    float vn = __fadd_rn(v, __fmul_rn(dt, c));
    float in = __fadd_rn(i, __fmul_rn(dt, __fmul_rn(nmu2, i)));
    float sn = __fadd_rn(s, __fmul_rn(dt, sg));
    v = vn; i = in; s = sn;
    out[ob]     = vn;
    out[ob + 1] = in;
    out[ob + 2] = sn;
}

__global__ void __launch_bounds__(32)
snn_phaseB(const float* __restrict__ ts, const float* __restrict__ inp,
           const float* __restrict__ mu, float* __restrict__ out,
           int T, int N)
{
    const int n = blockIdx.x * blockDim.x + threadIdx.x;
    if (n >= N) return;
    const int t0 = g_tstart;
    if (t0 >= T) return;

    const float dt   = __fsub_rn(ts[1], ts[0]);
    const float mu1  = mu[0];
    const float nmu2 = -mu[1];

    float v = g_sv[n];
    float i = g_si[n];
    float s = g_ss[n];

    int t = t0;
    float a0 = 0.f, a1 = 0.f, a2 = 0.f, a3 = 0.f;
    if (t + 0 < T) a0 = inp[(size_t)(t + 0) * N + n];
    if (t + 1 < T) a1 = inp[(size_t)(t + 1) * N + n];
    if (t + 2 < T) a2 = inp[(size_t)(t + 2) * N + n];
    if (t + 3 < T) a3 = inp[(size_t)(t + 3) * N + n];

    for (; t + 4 <= T; t += 4) {
        float b0 = 0.f, b1 = 0.f, b2 = 0.f, b3 = 0.f;
        if (t + 4 < T) b0 = inp[(size_t)(t + 4) * N + n];
        if (t + 5 < T) b1 = inp[(size_t)(t + 5) * N + n];
        if (t + 6 < T) b2 = inp[(size_t)(t + 6) * N + n];
        if (t + 7 < T) b3 = inp[(size_t)(t + 7) * N + n];

        stepB_store(dt, mu1, nmu2, a0, v, i, s, out, ((size_t)(t + 0) * N + n) * 3);
        stepB_store(dt, mu1, nmu2, a1, v, i, s, out, ((size_t)(t + 1) * N + n) * 3);
        stepB_store(dt, mu1, nmu2, a2, v, i, s, out, ((size_t)(t + 2) * N + n) * 3);
        stepB_store(dt, mu1, nmu2, a3, v, i, s, out, ((size_t)(t + 3) * N + n) * 3);

        a0 = b0; a1 = b1; a2 = b2; a3 = b3;
    }
    for (; t < T; ++t) {
        float c = inp[(size_t)t * N + n];
        stepB_store(dt, mu1, nmu2, c, v, i, s, out, ((size_t)t * N + n) * 3);
    }
}

// ---------------------------------------------------------------------------
extern "C" void kernel_launch(void* const* d_in, const int* in_sizes, int n_in,
                              void* d_out, int out_size)
{
    const float* ts  = (const float*)d_in[0];
    const float* inp = (const float*)d_in[1];
    const float* w   = (const float*)d_in[2];
    const float* v0  = (const float*)d_in[3];
    const float* i0  = (const float*)d_in[4];
    const float* mu  = (const float*)d_in[5];
    const float* s0u = (const float*)d_in[6];
    const float* ru  = (const float*)d_in[7];
    const int*   msp = (const int*)d_in[8];
    float* out = (float*)d_out;

    const int T = in_sizes[0];        // ts has T elements
    const int N = in_sizes[3];        // v0 has N elements (4096)

    snn_phaseA<<<1, BLKA>>>(ts, inp, w, v0, i0, mu, s0u, ru, msp, out, T, N);

    const int blkB = 32;
    snn_phaseB<<<(N + blkB - 1) / blkB, blkB>>>(ts, inp, mu, out, T, N);
}

// round 3
// speedup vs baseline: 1.8913x; 1.8913x over previous
#include <cuda_runtime.h>
#include <cstdint>

// Dataset-fixed shapes: T=2048, N=4096, max_spikes=128.
#define NMAX   4096
#define TMAX   2048
#define CTAS   8
#define THRA   (NMAX / CTAS)      // 512 threads per phase-A CTA, 1 neuron/thread
#define CHUNK  128
#define NCMAX  ((TMAX + CHUNK - 1) / CHUNK)   // 16
#define IDXINF 0x7FFFFFFFu

// Persistent state between phases (static device globals: no allocation).
static __device__ float g_sv[NMAX];
static __device__ float g_si[NMAX];
static __device__ float g_ss[NMAX];
static __device__ int   g_tstart;

// Phase-B scan scratch.
static __device__ float g_P[NCMAX * NMAX];       // per-chunk input response for v
static __device__ float g_vstart[NCMAX * NMAX];
static __device__ float g_istart[NCMAX * NMAX];
static __device__ float g_ssum[NCMAX * NMAX];    // per-chunk sum of dt*sigmoid
static __device__ float g_sstart[NCMAX * NMAX];
static __device__ float g_spre[TMAX * NMAX];     // per-step local sigma prefix

__device__ __forceinline__ float sigmoid_acc(float x) {
    float e = expf(-x);
    float d = __fadd_rn(1.0f, e);
    return 1.0f / d;     // accurate IEEE divide: matches XLA to ~1-2 ulp
}

__device__ __forceinline__ uint32_t smem_u32(const void* p) {
    uint32_t a;
    asm("{ .reg .u64 t; cvta.to.shared.u64 t, %1; cvt.u32.u64 %0, t; }"
        : "=r"(a) : "l"(p));
    return a;
}

__device__ __forceinline__ unsigned dsmem_ld_u32(uint32_t local_addr, unsigned rank) {
    uint32_t remote, val;
    asm volatile("mapa.shared::cluster.u32 %0, %1, %2;"
                 : "=r"(remote) : "r"(local_addr), "r"(rank));
    asm volatile("ld.shared::cluster.u32 %0, [%1];"
                 : "=r"(val) : "r"(remote) : "memory");
    return val;
}

// ---------------------------------------------------------------------------
// Phase A: coupled event phase. 8-CTA cluster, 1 neuron/thread, per-step
// cluster-wide min-index reduction through DSMEM mailboxes (parity buffered,
// one barrier.cluster per step). Exact-rounding math in the reference's
// expression order — the s>=0 crossing makes idx chaotic.
// ---------------------------------------------------------------------------
__global__ void __cluster_dims__(CTAS, 1, 1) __launch_bounds__(THRA, 1)
snn_phaseA(const float* __restrict__ ts, const float* __restrict__ inp,
           const float* __restrict__ w, const float* __restrict__ v0,
           const float* __restrict__ i0, const float* __restrict__ mu,
           const float* __restrict__ s0u, const float* __restrict__ ru,
           const int* __restrict__ msp, float* __restrict__ out,
           int T, int N)
{
    __shared__ unsigned sh_warpmin[THRA / 32];
    __shared__ unsigned sh_mb[2];        // per-CTA mailbox, parity buffered
    __shared__ unsigned sh_res;

    unsigned rank;
    asm("mov.u32 %0, %%cluster_ctarank;" : "=r"(rank));

    const int tid  = threadIdx.x;
    const int lane = tid & 31;
    const int wid  = tid >> 5;
    const int n    = (int)rank * THRA + tid;

    const float dt   = __fsub_rn(ts[1], ts[0]);
    const float mu1  = mu[0];
    const float nmu2 = -mu[1];
    const int max_spikes = msp[0];
    const uint32_t mb_addr = smem_u32(sh_mb);

    float v = v0[n];
    float i = i0[n];
    float s = __fsub_rn(logf(__fadd_rn(s0u[n], 1e-12f)), 0.01f);
    float cin = inp[n];                  // input row t = 0

    int nsp = 0;
    int t_end = T;

    for (int t = 0; t < T; ++t) {
        // Prefetch next input element (clamped).
        const int tn = (t + 1 < T) ? t + 1 : T - 1;
        float nin = inp[(size_t)tn * N + n];

        // s first (it feeds the reduction) — sigmoid of OLD v.
        const float sg = sigmoid_acc(v);
        const float sn0 = __fadd_rn(s, __fmul_rn(dt, sg));
        const bool  cross = (sn0 >= 0.0f);

        // Local min-index reduction over crossing neurons.
        unsigned lm = cross ? (unsigned)n : IDXINF;
        lm = __reduce_min_sync(0xFFFFFFFFu, lm);
        if (lane == 0) sh_warpmin[wid] = lm;

        // Speculative resample value for crossing lanes (hides logf in sync).
        float sjump = 0.0f;
        if (cross)
            sjump = __fsub_rn(logf(__fadd_rn(ru[(size_t)t * N + n], 1e-12f)), 0.01f);

        // v,i updates (independent of the reduction).
        const float d1 = __fsub_rn(i, v);
        const float va = __fmul_rn(mu1, d1);
        const float vb = __fmul_rn(mu1, cin);
        const float vc = __fadd_rn(va, vb);
        float vn = __fadd_rn(v, __fmul_rn(dt, vc));
        float in = __fadd_rn(i, __fmul_rn(dt, __fmul_rn(nmu2, i)));
        float sn = sn0;

        __syncthreads();
        if (wid == 0) {
            unsigned m = (lane < THRA / 32) ? sh_warpmin[lane] : IDXINF;
            m = __reduce_min_sync(0xFFFFFFFFu, m);
            if (lane == 0) sh_mb[t & 1] = m;
        }

        // One cluster barrier per step: orders own mailbox write (release)
        // before peers' reads (acquire). Parity buffering makes the write of
        // iteration t+2 safe against stragglers still reading iteration t.
        asm volatile("barrier.cluster.arrive.aligned;" ::: "memory");
        asm volatile("barrier.cluster.wait.aligned;" ::: "memory");

        if (wid == 0) {
            unsigned pm = IDXINF;
            if (lane < CTAS) pm = dsmem_ld_u32(mb_addr + 4u * (t & 1), (unsigned)lane);
            pm = __reduce_min_sync(0xFFFFFFFFu, pm);
            if (lane == 0) sh_res = pm;
        }
        __syncthreads();

        const unsigned idx = sh_res;
        const bool fire = (idx != IDXINF) && (nsp < max_spikes);

        if (fire) {
            if (cross) {
                vn = __fsub_rn(vn, 1.0f);     // V_RESET
                sn = sjump;
            } else {
                in = __fadd_rn(in, w[(size_t)idx * N + n]);
            }
            ++nsp;
        }

        v = vn; i = in; s = sn;

        float* op = out + ((size_t)t * N + n) * 3;
        op[0] = v; op[1] = i; op[2] = s;

        cin = nin;
        if (nsp >= max_spikes) { t_end = t + 1; break; }   // cluster-uniform
    }

    g_sv[n] = v; g_si[n] = i; g_ss[n] = s;
    if (rank == 0 && tid == 0) g_tstart = t_end;
}

// ---------------------------------------------------------------------------
// Phase B (fire permanently false): blocked parallel scan over t.
//   step map (algebraic):  v' = a*v + b*(i + inp_t);  i' = r*i;  s' = s + dt*sig(v)
//   with a = 1 - dt*mu1, b = dt*mu1, r = 1 - dt*mu2.
// ---------------------------------------------------------------------------

// B1: per (chunk, neuron) input response P (v evolved from v=0, i=0).
__global__ void snn_B1(const float* __restrict__ ts, const float* __restrict__ inp,
                       const float* __restrict__ mu, int T, int N)
{
    const int n = blockIdx.x * blockDim.x + threadIdx.x;
    const int c = blockIdx.y;
    const int t0 = g_tstart;
    const int tb = t0 + c * CHUNK;
    if (n >= N || tb >= T) return;
    const int te = (tb + CHUNK < T) ? tb + CHUNK : T;

    const float dt = ts[1] - ts[0];
    const float a  = 1.0f - dt * mu[0];
    const float b  = dt * mu[0];

    float P = 0.0f;
    for (int t = tb; t < te; ++t)
        P = a * P + b * inp[(size_t)t * N + n];
    g_P[c * NMAX + n] = P;
}

// B2: per-neuron sequential combine over chunks -> chunk-start (v, i).
__global__ void snn_B2(const float* __restrict__ ts, const float* __restrict__ mu,
                       int T, int N)
{
    const int n = blockIdx.x * blockDim.x + threadIdx.x;
    if (n >= N) return;
    const int t0 = g_tstart;
    if (t0 >= T) return;
    const int NC = (T - t0 + CHUNK - 1) / CHUNK;

    const float dt = ts[1] - ts[0];
    const float a  = 1.0f - dt * mu[0];
    const float b  = dt * mu[0];
    const float r  = 1.0f - dt * mu[1];

    // Full-chunk composed scalars: after CHUNK steps,
    //   v_end = A*v0 + Q*i0 + P ,  i_end = R*i0.
    float A = 1.0f, Q = 0.0f, R = 1.0f;
    #pragma unroll 8
    for (int j = 0; j < CHUNK; ++j) { Q = a * Q + b * R; A *= a; R *= r; }

    float v = g_sv[n];
    float i = g_si[n];
    for (int c = 0; c < NC; ++c) {
        g_vstart[c * NMAX + n] = v;
        g_istart[c * NMAX + n] = i;
        if (c < NC - 1) {
            const float vn = A * v + Q * i + g_P[c * NMAX + n];
            i = R * i;
            v = vn;
        }
    }
}

// B3: re-simulate each chunk from its known start with the reference's exact
// rounding; write v,i to out and the local dt*sigmoid prefix to scratch.
__global__ void snn_B3(const float* __restrict__ ts, const float* __restrict__ inp,
                       const float* __restrict__ mu, float* __restrict__ out,
                       int T, int N)
{
    const int n = blockIdx.x * blockDim.x + threadIdx.x;
    const int c = blockIdx.y;
    const int t0 = g_tstart;
    const int tb = t0 + c * CHUNK;
    if (n >= N || tb >= T) return;
    const int te = (tb + CHUNK < T) ? tb + CHUNK : T;

    const float dt   = __fsub_rn(ts[1], ts[0]);
    const float mu1  = mu[0];
    const float nmu2 = -mu[1];

    float v = g_vstart[c * NMAX + n];
    float i = g_istart[c * NMAX + n];
    float spre = 0.0f;

    for (int t = tb; t < te; ++t) {
        const float cin = inp[(size_t)t * N + n];
        const float sg  = sigmoid_acc(v);                 // sigmoid of OLD v
        const float d1  = __fsub_rn(i, v);
        const float va  = __fmul_rn(mu1, d1);
        const float vb  = __fmul_rn(mu1, cin);
        const float vc  = __fadd_rn(va, vb);
        v = __fadd_rn(v, __fmul_rn(dt, vc));
        i = __fadd_rn(i, __fmul_rn(dt, __fmul_rn(nmu2, i)));
        spre = __fadd_rn(spre, __fmul_rn(dt, sg));

        float* op = out + ((size_t)t * N + n) * 3;
        op[0] = v; op[1] = i;
        g_spre[(size_t)t * N + n] = spre;
    }
    g_ssum[c * NMAX + n] = spre;
}

// B4: per-neuron scan of chunk sigma-sums -> chunk-start s.
__global__ void snn_B4(int T, int N)
{
    const int n = blockIdx.x * blockDim.x + threadIdx.x;
    if (n >= N) return;
    const int t0 = g_tstart;
    if (t0 >= T) return;
    const int NC = (T - t0 + CHUNK - 1) / CHUNK;

    float s = g_ss[n];
    for (int c = 0; c < NC; ++c) {
        g_sstart[c * NMAX + n] = s;
        s += g_ssum[c * NMAX + n];
    }
}

// B5: finalize s outputs.
__global__ void snn_B5(float* __restrict__ out, int T, int N)
{
    const int t0 = g_tstart;
    const int c  = blockIdx.y;
    const int e  = blockIdx.x * blockDim.x + threadIdx.x;   // [0, CHUNK*N)
    const int tb = t0 + c * CHUNK;
    const int t  = tb + e / N;
    const int n  = e - (e / N) * N;
    if (t >= T || tb >= T) return;

    out[((size_t)t * N + n) * 3 + 2] = g_sstart[c * NMAX + n] + g_spre[(size_t)t * N + n];
}

// ---------------------------------------------------------------------------
extern "C" void kernel_launch(void* const* d_in, const int* in_sizes, int n_in,
                              void* d_out, int out_size)
{
    const float* ts  = (const float*)d_in[0];
    const float* inp = (const float*)d_in[1];
    const float* w   = (const float*)d_in[2];
    const float* v0  = (const float*)d_in[3];
    const float* i0  = (const float*)d_in[4];
    const float* mu  = (const float*)d_in[5];
    const float* s0u = (const float*)d_in[6];
    const float* ru  = (const float*)d_in[7];
    const int*   msp = (const int*)d_in[8];
    float* out = (float*)d_out;

    const int T = in_sizes[0];
    const int N = in_sizes[3];

    snn_phaseA<<<CTAS, THRA>>>(ts, inp, w, v0, i0, mu, s0u, ru, msp, out, T, N);

    const int NC = (T + CHUNK - 1) / CHUNK;    // upper bound on chunks needed
    dim3 gB1((N + 255) / 256, NC);
    snn_B1<<<gB1, 256>>>(ts, inp, mu, T, N);
    snn_B2<<<(N + 255) / 256, 256>>>(ts, mu, T, N);
    snn_B3<<<gB1, 256>>>(ts, inp, mu, out, T, N);
    snn_B4<<<(N + 255) / 256, 256>>>(T, N);
    dim3 gB5((CHUNK * N) / 256, NC);
    snn_B5<<<gB5, 256>>>(out, T, N);
}

// round 4
// speedup vs baseline: 2.8254x; 1.4939x over previous
#include <cuda_runtime.h>
#include <cstdint>

// Dataset-fixed shapes: T=2048, N=4096, max_spikes=128.
#define NMAX   4096
#define TMAX   2048
#define CTAS   8
#define THRA   (NMAX / CTAS)      // 512 threads per phase-A CTA, 1 neuron/thread
#define CHUNK  64
#define NCMAX  (TMAX / CHUNK)     // 32 (covers worst case t0 = 0)
#define IDXINF 0x7FFFFFFFu

// Persistent state between phases (static device globals: no allocation).
static __device__ float g_sv[NMAX];
static __device__ float g_si[NMAX];
static __device__ float g_ss[NMAX];
static __device__ int   g_tstart;

// Phase-B scan scratch.
static __device__ float g_P[NCMAX * NMAX];       // per-chunk input response for v
static __device__ float g_vstart[NCMAX * NMAX];
static __device__ float g_istart[NCMAX * NMAX];
static __device__ float g_ssum[NCMAX * NMAX];    // per-chunk sum of dt*sigmoid
static __device__ float g_sstart[NCMAX * NMAX];

__device__ __forceinline__ float sigmoid_acc(float x) {
    float e = expf(-x);
    float d = __fadd_rn(1.0f, e);
    return 1.0f / d;     // accurate IEEE divide: matches XLA to ~1-2 ulp
}

__device__ __forceinline__ uint32_t smem_u32(const void* p) {
    uint32_t a;
    asm("{ .reg .u64 t; cvta.to.shared.u64 t, %1; cvt.u32.u64 %0, t; }"
        : "=r"(a) : "l"(p));
    return a;
}

__device__ __forceinline__ uint32_t mapa_u32(uint32_t local_addr, unsigned rank) {
    uint32_t remote;
    asm("mapa.shared::cluster.u32 %0, %1, %2;"
        : "=r"(remote) : "r"(local_addr), "r"(rank));
    return remote;
}

__device__ __forceinline__ void mbar_arrive_expect_tx(uint32_t mbar, unsigned tx) {
    asm volatile("mbarrier.arrive.expect_tx.shared.b64 _, [%0], %1;"
                 :: "r"(mbar), "r"(tx) : "memory");
}

// Push 4B into a peer CTA's smem slot and signal its mbarrier (tx += 4).
__device__ __forceinline__ void st_async_u32(uint32_t raddr, unsigned val, uint32_t rmbar) {
    asm volatile("st.async.shared::cluster.mbarrier::complete_tx::bytes.b32 [%0], %1, [%2];"
                 :: "r"(raddr), "r"(val), "r"(rmbar) : "memory");
}

__device__ __forceinline__ void mbar_wait_parity_cluster(uint32_t mbar, unsigned parity) {
    unsigned done;
    asm volatile(
        "{\n\t.reg .pred p;\n\t"
        "mbarrier.try_wait.parity.acquire.cluster.shared::cta.b64 p, [%1], %2;\n\t"
        "selp.b32 %0, 1, 0, p;\n\t}"
        : "=r"(done) : "r"(mbar), "r"(parity) : "memory");
    while (!done) {
        asm volatile(
            "{\n\t.reg .pred p;\n\t"
            "mbarrier.try_wait.parity.acquire.cluster.shared::cta.b64 p, [%1], %2, 0x989680;\n\t"
            "selp.b32 %0, 1, 0, p;\n\t}"
            : "=r"(done) : "r"(mbar), "r"(parity) : "memory");
    }
}

// ---------------------------------------------------------------------------
// Phase A: coupled event phase. 8-CTA cluster, 1 neuron/thread.
// Per step: local CTA min-reduce, push candidate to all 8 CTAs' mailboxes via
// st.async (parity double-buffered), local mbarrier wait, 8 LDS + min.
// The w[idx] row load and the i-finalization + output store of step t are
// DEFERRED to the top of step t+1, so the 577-cyc DRAM load sits off the
// inter-CTA critical cycle. Exact-rounding ops in the reference's order.
// ---------------------------------------------------------------------------
__global__ void __cluster_dims__(CTAS, 1, 1) __launch_bounds__(THRA, 1)
snn_phaseA(const float* __restrict__ ts, const float* __restrict__ inp,
           const float* __restrict__ w, const float* __restrict__ v0,
           const float* __restrict__ i0, const float* __restrict__ mu,
           const float* __restrict__ s0u, const float* __restrict__ ru,
           const int* __restrict__ msp, float* __restrict__ out,
           int T, int N)
{
    __shared__ unsigned sh_warpmin[THRA / 32];
    __shared__ unsigned sh_slots[2][CTAS];              // [parity][src_rank]
    __shared__ alignas(8) unsigned long long sh_mbar;

    unsigned rank;
    asm("mov.u32 %0, %%cluster_ctarank;" : "=r"(rank));

    const int tid  = threadIdx.x;
    const int lane = tid & 31;
    const int wid  = tid >> 5;
    const int n    = (int)rank * THRA + tid;

    const float dt   = __fsub_rn(ts[1], ts[0]);
    const float mu1  = mu[0];
    const float nmu2 = -mu[1];
    const int max_spikes = msp[0];

    const uint32_t slots_addr = smem_u32(sh_slots);
    const uint32_t mbar_addr  = smem_u32((const void*)&sh_mbar);

    if (tid == 0) {
        asm volatile("mbarrier.init.shared.b64 [%0], %1;"
                     :: "r"(mbar_addr), "r"(1u) : "memory");
    }
    __syncthreads();
    asm volatile("barrier.cluster.arrive.aligned;" ::: "memory");
    asm volatile("barrier.cluster.wait.aligned;" ::: "memory");

    float v    = v0[n];                  // final v of previous step
    float iPre = i0[n];                  // i of previous step, w-add may be pending
    float s    = __fsub_rn(logf(__fadd_rn(s0u[n], 1e-12f)), 0.01f);
    bool  pend = false;
    float wv   = 0.0f;
    float cin  = inp[n];                 // inp row t = 0

    int nsp = 0;
    int t_end = T;

    for (int t = 0; t < T; ++t) {
        // Early independent loads (latency hidden across the step).
        const float ruv = ru[(size_t)t * N + n];
        const int   tn  = (t + 1 < T) ? t + 1 : T - 1;
        const float nin = inp[(size_t)tn * N + n];

        // Threshold state first — it feeds the inter-CTA reduction.
        const float sg   = sigmoid_acc(v);                    // sigmoid of OLD v
        const float sn0  = __fadd_rn(s, __fmul_rn(dt, sg));
        const bool  cross = (sn0 >= 0.0f);

        unsigned lm = cross ? (unsigned)n : IDXINF;
        lm = __reduce_min_sync(0xFFFFFFFFu, lm);
        if (lane == 0) sh_warpmin[wid] = lm;
        __syncthreads();
        if (wid == 0) {
            unsigned m = (lane < THRA / 32) ? sh_warpmin[lane] : IDXINF;
            m = __reduce_min_sync(0xFFFFFFFFu, m);
            if (lane == 0) mbar_arrive_expect_tx(mbar_addr, 4u * CTAS);
            if (lane < CTAS) {
                const uint32_t la = slots_addr + ((unsigned)(t & 1) * CTAS + rank) * 4u;
                st_async_u32(mapa_u32(la, (unsigned)lane), m,
                             mapa_u32(mbar_addr, (unsigned)lane));
            }
        }

        // ---- deferred finalization of step t-1 (off the sync critical path) ----
        const float ifin = pend ? __fadd_rn(iPre, wv) : iPre;
        if (t > 0) {
            float* op = out + ((size_t)(t - 1) * N + n) * 3;
            op[0] = v; op[1] = ifin; op[2] = s;
        }

        // Pre-fire values for step t.
        const float d1 = __fsub_rn(ifin, v);
        const float va = __fmul_rn(mu1, d1);
        const float vb = __fmul_rn(mu1, cin);
        float vn = __fadd_rn(v, __fmul_rn(dt, __fadd_rn(va, vb)));
        float in = __fadd_rn(ifin, __fmul_rn(dt, __fmul_rn(nmu2, ifin)));
        float sn = sn0;
        const float sjump = __fsub_rn(logf(__fadd_rn(ruv, 1e-12f)), 0.01f);

        // Wait for all 8 candidates, gather from local smem.
        mbar_wait_parity_cluster(mbar_addr, (unsigned)(t & 1));
        unsigned idx = sh_slots[t & 1][0];
        #pragma unroll
        for (int r = 1; r < CTAS; ++r) idx = min(idx, sh_slots[t & 1][r]);

        const bool fire = (idx != IDXINF) && (nsp < max_spikes);
        pend = false;
        if (fire) {
            if (cross) {
                vn = __fsub_rn(vn, 1.0f);          // V_RESET
                sn = sjump;
            } else {
                pend = true;
                wv = w[(size_t)idx * N + n];       // 577-cyc load, slack ~2 steps
            }
            ++nsp;
        }

        v = vn; iPre = in; s = sn; cin = nin;
        if (nsp >= max_spikes) { t_end = t + 1; break; }    // cluster-uniform
    }

    // Epilogue: finalize and store the last computed row.
    const float ifin = pend ? __fadd_rn(iPre, wv) : iPre;
    {
        float* op = out + ((size_t)(t_end - 1) * N + n) * 3;
        op[0] = v; op[1] = ifin; op[2] = s;
    }
    g_sv[n] = v; g_si[n] = ifin; g_ss[n] = s;
    if (rank == 0 && tid == 0) g_tstart = t_end;
}

// ---------------------------------------------------------------------------
// Phase B (fire permanently false): blocked parallel scan over t.
//   v' = a*v + b*(i + inp_t);  i' = r*i;  s' = s + dt*sigmoid(v)
//   a = 1 - dt*mu1, b = dt*mu1, r = 1 - dt*mu2.
// ---------------------------------------------------------------------------

// B1: per (chunk, neuron) input response P (v evolved from v=0, i=0).
__global__ void snn_B1(const float* __restrict__ ts, const float* __restrict__ inp,
                       const float* __restrict__ mu, int T, int N)
{
    const int n = blockIdx.x * blockDim.x + threadIdx.x;
    const int c = blockIdx.y;
    const int t0 = g_tstart;
    const int tb = t0 + c * CHUNK;
    if (n >= N || tb >= T) return;
    const int te = (tb + CHUNK < T) ? tb + CHUNK : T;

    const float dt = ts[1] - ts[0];
    const float a  = 1.0f - dt * mu[0];
    const float b  = dt * mu[0];

    float P = 0.0f;
    int t = tb;
    for (; t + 4 <= te; t += 4) {               // batched loads -> MLP 4
        const float x0 = inp[(size_t)(t + 0) * N + n];
        const float x1 = inp[(size_t)(t + 1) * N + n];
        const float x2 = inp[(size_t)(t + 2) * N + n];
        const float x3 = inp[(size_t)(t + 3) * N + n];
        P = __fmaf_rn(a, P, b * x0);
        P = __fmaf_rn(a, P, b * x1);
        P = __fmaf_rn(a, P, b * x2);
        P = __fmaf_rn(a, P, b * x3);
    }
    for (; t < te; ++t)
        P = __fmaf_rn(a, P, b * inp[(size_t)t * N + n]);
    g_P[c * NMAX + n] = P;
}

// B2: per-neuron combine over chunks -> chunk-start (v, i).
__global__ void snn_B2(const float* __restrict__ ts, const float* __restrict__ mu,
                       int T, int N)
{
    const int n = blockIdx.x * blockDim.x + threadIdx.x;
    if (n >= N) return;
    const int t0 = g_tstart;
    if (t0 >= T) return;
    const int NC = (T - t0 + CHUNK - 1) / CHUNK;

    const float dt = ts[1] - ts[0];
    const float a  = 1.0f - dt * mu[0];
    const float b  = dt * mu[0];
    const float r  = 1.0f - dt * mu[1];

    // Full-chunk composed scalars: v_end = A*v0 + Q*i0 + P, i_end = R*i0.
    float A = 1.0f, Q = 0.0f, R = 1.0f;
    #pragma unroll 8
    for (int j = 0; j < CHUNK; ++j) { Q = a * Q + b * R; A *= a; R *= r; }

    float v = g_sv[n];
    float i = g_si[n];
    for (int c = 0; c < NC; ++c) {
        g_vstart[c * NMAX + n] = v;
        g_istart[c * NMAX + n] = i;
        if (c < NC - 1) {
            const float vn = A * v + Q * i + g_P[c * NMAX + n];
            i = R * i;
            v = vn;
        }
    }
}

// One exact-rounded reference step (sigmoid of OLD v).
__device__ __forceinline__ void stepX(float dt, float mu1, float nmu2, float cin,
                                      float& v, float& i, float& spre)
{
    const float sg = sigmoid_acc(v);
    const float d1 = __fsub_rn(i, v);
    const float va = __fmul_rn(mu1, d1);
    const float vb = __fmul_rn(mu1, cin);
    v = __fadd_rn(v, __fmul_rn(dt, __fadd_rn(va, vb)));
    i = __fadd_rn(i, __fmul_rn(dt, __fmul_rn(nmu2, i)));
    spre = __fadd_rn(spre, __fmul_rn(dt, sg));
}

// B3a: simulate chunk -> per-chunk sigma sum only (no output traffic).
__global__ void snn_B3a(const float* __restrict__ ts, const float* __restrict__ inp,
                        const float* __restrict__ mu, int T, int N)
{
    const int n = blockIdx.x * blockDim.x + threadIdx.x;
    const int c = blockIdx.y;
    const int t0 = g_tstart;
    const int tb = t0 + c * CHUNK;
    if (n >= N || tb >= T) return;
    const int te = (tb + CHUNK < T) ? tb + CHUNK : T;

    const float dt   = __fsub_rn(ts[1], ts[0]);
    const float mu1  = mu[0];
    const float nmu2 = -mu[1];

    float v = g_vstart[c * NMAX + n];
    float i = g_istart[c * NMAX + n];
    float spre = 0.0f;

    int t = tb;
    for (; t + 4 <= te; t += 4) {
        const float x0 = inp[(size_t)(t + 0) * N + n];
        const float x1 = inp[(size_t)(t + 1) * N + n];
        const float x2 = inp[(size_t)(t + 2) * N + n];
        const float x3 = inp[(size_t)(t + 3) * N + n];
        stepX(dt, mu1, nmu2, x0, v, i, spre);
        stepX(dt, mu1, nmu2, x1, v, i, spre);
        stepX(dt, mu1, nmu2, x2, v, i, spre);
        stepX(dt, mu1, nmu2, x3, v, i, spre);
    }
    for (; t < te; ++t)
        stepX(dt, mu1, nmu2, inp[(size_t)t * N + n], v, i, spre);

    g_ssum[c * NMAX + n] = spre;
}

// B4: per-neuron scan of chunk sigma-sums -> chunk-start s.
__global__ void snn_B4(int T, int N)
{
    const int n = blockIdx.x * blockDim.x + threadIdx.x;
    if (n >= N) return;
    const int t0 = g_tstart;
    if (t0 >= T) return;
    const int NC = (T - t0 + CHUNK - 1) / CHUNK;

    float s = g_ss[n];
    for (int c = 0; c < NC; ++c) {
        g_sstart[c * NMAX + n] = s;
        s += g_ssum[c * NMAX + n];
    }
}

// B3b: re-simulate each chunk, write (v,i,s) as one contiguous 12B record.
__global__ void snn_B3b(const float* __restrict__ ts, const float* __restrict__ inp,
                        const float* __restrict__ mu, float* __restrict__ out,
                        int T, int N)
{
    const int n = blockIdx.x * blockDim.x + threadIdx.x;
    const int c = blockIdx.y;
    const int t0 = g_tstart;
    const int tb = t0 + c * CHUNK;
    if (n >= N || tb >= T) return;
    const int te = (tb + CHUNK < T) ? tb + CHUNK : T;

    const float dt   = __fsub_rn(ts[1], ts[0]);
    const float mu1  = mu[0];
    const float nmu2 = -mu[1];

    float v = g_vstart[c * NMAX + n];
    float i = g_istart[c * NMAX + n];
    const float sstart = g_sstart[c * NMAX + n];
    float spre = 0.0f;

    int t = tb;
    for (; t + 2 <= te; t += 2) {
        const float x0 = inp[(size_t)(t + 0) * N + n];
        const float x1 = inp[(size_t)(t + 1) * N + n];

        stepX(dt, mu1, nmu2, x0, v, i, spre);
        float* op0 = out + ((size_t)(t + 0) * N + n) * 3;
        op0[0] = v; op0[1] = i; op0[2] = __fadd_rn(sstart, spre);

        stepX(dt, mu1, nmu2, x1, v, i, spre);
        float* op1 = out + ((size_t)(t + 1) * N + n) * 3;
        op1[0] = v; op1[1] = i; op1[2] = __fadd_rn(sstart, spre);
    }
    for (; t < te; ++t) {
        stepX(dt, mu1, nmu2, inp[(size_t)t * N + n], v, i, spre);
        float* op = out + ((size_t)t * N + n) * 3;
        op[0] = v; op[1] = i; op[2] = __fadd_rn(sstart, spre);
    }
}

// ---------------------------------------------------------------------------
extern "C" void kernel_launch(void* const* d_in, const int* in_sizes, int n_in,
                              void* d_out, int out_size)
{
    const float* ts  = (const float*)d_in[0];
    const float* inp = (const float*)d_in[1];
    const float* w   = (const float*)d_in[2];
    const float* v0  = (const float*)d_in[3];
    const float* i0  = (const float*)d_in[4];
    const float* mu  = (const float*)d_in[5];
    const float* s0u = (const float*)d_in[6];
    const float* ru  = (const float*)d_in[7];
    const int*   msp = (const int*)d_in[8];
    float* out = (float*)d_out;

    const int T = in_sizes[0];
    const int N = in_sizes[3];

    snn_phaseA<<<CTAS, THRA>>>(ts, inp, w, v0, i0, mu, s0u, ru, msp, out, T, N);

    dim3 gB((N + 255) / 256, NCMAX);
    snn_B1 <<<gB, 256>>>(ts, inp, mu, T, N);
    snn_B2 <<<(N + 255) / 256, 256>>>(ts, mu, T, N);
    snn_B3a<<<gB, 256>>>(ts, inp, mu, T, N);
    snn_B4 <<<(N + 255) / 256, 256>>>(T, N);
    snn_B3b<<<gB, 256>>>(ts, inp, mu, out, T, N);
}

// round 9
// speedup vs baseline: 2.8836x; 1.0206x over previous
#include <cuda_runtime.h>
#include <cstdint>

// Dataset-fixed shapes: T=2048, N=4096, max_spikes=128.
#define NMAX   4096
#define TMAX   2048
#define CTAS   8
#define THRA   (NMAX / CTAS)      // 512 threads per phase-A CTA, 1 neuron/thread
#define CHUNK  32
#define NCMAX  (TMAX / CHUNK)     // 64 (covers worst case t0 = 0)
#define IDXINF 0x7FFFFFFFu

// Persistent state between phases (static device globals: no allocation).
static __device__ float g_sv[NMAX];
static __device__ float g_si[NMAX];
static __device__ float g_ss[NMAX];
static __device__ int   g_tstart;

// Phase-B scan scratch.
static __device__ float g_P[NCMAX * NMAX];
static __device__ float g_vstart[NCMAX * NMAX];
static __device__ float g_istart[NCMAX * NMAX];
static __device__ float g_ssum[NCMAX * NMAX];
static __device__ float g_sstart[NCMAX * NMAX];

__device__ __forceinline__ float sigmoid_acc(float x) {
    float e = expf(-x);
    float d = __fadd_rn(1.0f, e);
    return 1.0f / d;     // accurate: matches reference to ~1-2 ulp (validated)
}
__device__ __forceinline__ float sigmoid_fast(float x) {
    return __fdividef(1.0f, 1.0f + __expf(-x));   // phase B only (no thresholds)
}

__device__ __forceinline__ uint32_t smem_u32(const void* p) {
    uint32_t a;
    asm("{ .reg .u64 t; cvta.to.shared.u64 t, %1; cvt.u32.u64 %0, t; }"
        : "=r"(a) : "l"(p));
    return a;
}

__device__ __forceinline__ uint32_t mapa_u32(uint32_t local_addr, unsigned rank) {
    uint32_t remote;
    asm("mapa.shared::cluster.u32 %0, %1, %2;"
        : "=r"(remote) : "r"(local_addr), "r"(rank));
    return remote;
}

__device__ __forceinline__ void mbar_arrive_expect_tx(uint32_t mbar, unsigned tx) {
    asm volatile("mbarrier.arrive.expect_tx.shared.b64 _, [%0], %1;"
                 :: "r"(mbar), "r"(tx) : "memory");
}

// Push 4B into a peer CTA's smem slot and signal its mbarrier (tx += 4).
__device__ __forceinline__ void st_async_u32(uint32_t raddr, unsigned val, uint32_t rmbar) {
    asm volatile("st.async.shared::cluster.mbarrier::complete_tx::bytes.b32 [%0], %1, [%2];"
                 :: "r"(raddr), "r"(val), "r"(rmbar) : "memory");
}

__device__ __forceinline__ void mbar_wait_parity_cluster(uint32_t mbar, unsigned parity) {
    unsigned done;
    asm volatile(
        "{\n\t.reg .pred p;\n\t"
        "mbarrier.try_wait.parity.acquire.cluster.shared::cta.b64 p, [%1], %2;\n\t"
        "selp.b32 %0, 1, 0, p;\n\t}"
        : "=r"(done) : "r"(mbar), "r"(parity) : "memory");
    while (!done) {
        asm volatile(
            "{\n\t.reg .pred p;\n\t"
            "mbarrier.try_wait.parity.acquire.cluster.shared::cta.b64 p, [%1], %2, 0x989680;\n\t"
            "selp.b32 %0, 1, 0, p;\n\t}"
            : "=r"(done) : "r"(mbar), "r"(parity) : "memory");
    }
}

// ---------------------------------------------------------------------------
// Phase A: coupled event phase. 8-CTA cluster, 1 neuron/thread.
// VERBATIM the R4-passing kernel (295us, rel_err 1.3e-6): per step local CTA
// min-reduce, push candidate to all 8 CTAs' mailboxes via st.async (parity
// double-buffered), local mbarrier wait, 8 LDS + min. w[idx] row load and
// i-finalization + output store of step t deferred to the top of step t+1.
// Exact-rounding ops in the reference's expression order.
// ---------------------------------------------------------------------------
__global__ void __cluster_dims__(CTAS, 1, 1) __launch_bounds__(THRA, 1)
snn_phaseA(const float* __restrict__ ts, const float* __restrict__ inp,
           const float* __restrict__ w, const float* __restrict__ v0,
           const float* __restrict__ i0, const float* __restrict__ mu,
           const float* __restrict__ s0u, const float* __restrict__ ru,
           const int* __restrict__ msp, float* __restrict__ out,
           int T, int N)
{
    __shared__ unsigned sh_warpmin[THRA / 32];
    __shared__ unsigned sh_slots[2][CTAS];              // [parity][src_rank]
    __shared__ alignas(8) unsigned long long sh_mbar;

    unsigned rank;
    asm("mov.u32 %0, %%cluster_ctarank;" : "=r"(rank));

    const int tid  = threadIdx.x;
    const int lane = tid & 31;
    const int wid  = tid >> 5;
    const int n    = (int)rank * THRA + tid;

    const float dt   = __fsub_rn(ts[1], ts[0]);
    const float mu1  = mu[0];
    const float nmu2 = -mu[1];
    const int max_spikes = msp[0];

    const uint32_t slots_addr = smem_u32(sh_slots);
    const uint32_t mbar_addr  = smem_u32((const void*)&sh_mbar);

    if (tid == 0) {
        asm volatile("mbarrier.init.shared.b64 [%0], %1;"
                     :: "r"(mbar_addr), "r"(1u) : "memory");
    }
    __syncthreads();
    asm volatile("barrier.cluster.arrive.aligned;" ::: "memory");
    asm volatile("barrier.cluster.wait.aligned;" ::: "memory");

    float v    = v0[n];                  // final v of previous step
    float iPre = i0[n];                  // i of previous step, w-add may be pending
    float s    = __fsub_rn(logf(__fadd_rn(s0u[n], 1e-12f)), 0.01f);
    bool  pend = false;
    float wv   = 0.0f;
    float cin  = inp[n];                 // inp row t = 0

    int nsp = 0;
    int t_end = T;

    for (int t = 0; t < T; ++t) {
        // Early independent loads (latency hidden across the step).
        const float ruv = ru[(size_t)t * N + n];
        const int   tn  = (t + 1 < T) ? t + 1 : T - 1;
        const float nin = inp[(size_t)tn * N + n];

        // Threshold state first — it feeds the inter-CTA reduction.
        const float sg   = sigmoid_acc(v);                    // sigmoid of OLD v
        const float sn0  = __fadd_rn(s, __fmul_rn(dt, sg));
        const bool  cross = (sn0 >= 0.0f);

        unsigned lm = cross ? (unsigned)n : IDXINF;
        lm = __reduce_min_sync(0xFFFFFFFFu, lm);
        if (lane == 0) sh_warpmin[wid] = lm;
        __syncthreads();
        if (wid == 0) {
            unsigned m = (lane < THRA / 32) ? sh_warpmin[lane] : IDXINF;
            m = __reduce_min_sync(0xFFFFFFFFu, m);
            if (lane == 0) mbar_arrive_expect_tx(mbar_addr, 4u * CTAS);
            if (lane < CTAS) {
                const uint32_t la = slots_addr + ((unsigned)(t & 1) * CTAS + rank) * 4u;
                st_async_u32(mapa_u32(la, (unsigned)lane), m,
                             mapa_u32(mbar_addr, (unsigned)lane));
            }
        }

        // ---- deferred finalization of step t-1 (off the sync critical path) ----
        const float ifin = pend ? __fadd_rn(iPre, wv) : iPre;
        if (t > 0) {
            float* op = out + ((size_t)(t - 1) * N + n) * 3;
            op[0] = v; op[1] = ifin; op[2] = s;
        }

        // Pre-fire values for step t.
        const float d1 = __fsub_rn(ifin, v);
        const float va = __fmul_rn(mu1, d1);
        const float vb = __fmul_rn(mu1, cin);
        float vn = __fadd_rn(v, __fmul_rn(dt, __fadd_rn(va, vb)));
        float in = __fadd_rn(ifin, __fmul_rn(dt, __fmul_rn(nmu2, ifin)));
        float sn = sn0;
        const float sjump = __fsub_rn(logf(__fadd_rn(ruv, 1e-12f)), 0.01f);

        // Wait for all 8 candidates, gather from local smem.
        mbar_wait_parity_cluster(mbar_addr, (unsigned)(t & 1));
        unsigned idx = sh_slots[t & 1][0];
        #pragma unroll
        for (int r = 1; r < CTAS; ++r) idx = min(idx, sh_slots[t & 1][r]);

        const bool fire = (idx != IDXINF) && (nsp < max_spikes);
        pend = false;
        if (fire) {
            if (cross) {
                vn = __fsub_rn(vn, 1.0f);          // V_RESET
                sn = sjump;
            } else {
                pend = true;
                wv = w[(size_t)idx * N + n];       // 577-cyc load, slack ~2 steps
            }
            ++nsp;
        }

        v = vn; iPre = in; s = sn; cin = nin;
        if (nsp >= max_spikes) { t_end = t + 1; break; }    // cluster-uniform
    }

    // Epilogue: finalize and store the last computed row.
    const float ifin = pend ? __fadd_rn(iPre, wv) : iPre;
    {
        float* op = out + ((size_t)(t_end - 1) * N + n) * 3;
        op[0] = v; op[1] = ifin; op[2] = s;
    }
    g_sv[n] = v; g_si[n] = ifin; g_ss[n] = s;
    if (rank == 0 && tid == 0) g_tstart = t_end;
}

// ---------------------------------------------------------------------------
// Phase B (fire permanently false): blocked parallel scan over t.
//   v' = a*v + b*(i + inp_t);  i' = r*i;  s' = s + dt*sigmoid(v)
//   a = 1 - dt*mu1, b = dt*mu1, r = 1 - dt*mu2.
// No thresholds -> fast-math sigmoid and FMA contraction are safe (output
// perturbation ~1e-7 rel vs 1e-3 tolerance).
// ---------------------------------------------------------------------------

// B1: per (chunk, neuron) input response P (v evolved from v=0, i=0).
__global__ void snn_B1(const float* __restrict__ ts, const float* __restrict__ inp,
                       const float* __restrict__ mu, int T, int N)
{
    const int n = blockIdx.x * blockDim.x + threadIdx.x;
    const int c = blockIdx.y;
    const int t0 = g_tstart;
    const int tb = t0 + c * CHUNK;
    if (n >= N || tb >= T) return;
    const int te = (tb + CHUNK < T) ? tb + CHUNK : T;

    const float dt = ts[1] - ts[0];
    const float a  = 1.0f - dt * mu[0];
    const float b  = dt * mu[0];

    float P = 0.0f;
    int t = tb;
    for (; t + 4 <= te; t += 4) {
        const float x0 = inp[(size_t)(t + 0) * N + n];
        const float x1 = inp[(size_t)(t + 1) * N + n];
        const float x2 = inp[(size_t)(t + 2) * N + n];
        const float x3 = inp[(size_t)(t + 3) * N + n];
        P = __fmaf_rn(a, P, b * x0);
        P = __fmaf_rn(a, P, b * x1);
        P = __fmaf_rn(a, P, b * x2);
        P = __fmaf_rn(a, P, b * x3);
    }
    for (; t < te; ++t)
        P = __fmaf_rn(a, P, b * inp[(size_t)t * N + n]);
    g_P[c * NMAX + n] = P;
}

// B2: per-neuron combine over chunks -> chunk-start (v, i).
__global__ void snn_B2(const float* __restrict__ ts, const float* __restrict__ mu,
                       int T, int N)
{
    const int n = blockIdx.x * blockDim.x + threadIdx.x;
    if (n >= N) return;
    const int t0 = g_tstart;
    if (t0 >= T) return;
    const int NC = (T - t0 + CHUNK - 1) / CHUNK;

    const float dt = ts[1] - ts[0];
    const float a  = 1.0f - dt * mu[0];
    const float b  = dt * mu[0];
    const float r  = 1.0f - dt * mu[1];

    // Full-chunk composed scalars: v_end = A*v0 + Q*i0 + P, i_end = R*i0.
    float A = 1.0f, Q = 0.0f, R = 1.0f;
    #pragma unroll 8
    for (int j = 0; j < CHUNK; ++j) { Q = a * Q + b * R; A *= a; R *= r; }

    float v = g_sv[n];
    float i = g_si[n];
    for (int c = 0; c < NC; ++c) {
        g_vstart[c * NMAX + n] = v;
        g_istart[c * NMAX + n] = i;
        if (c < NC - 1) {
            const float vn = A * v + Q * i + g_P[c * NMAX + n];
            i = R * i;
            v = vn;
        }
    }
}

// One fast step (sigmoid of OLD v); phase B only.
__device__ __forceinline__ void stepF(float dt, float mu1, float nmu2, float cin,
                                      float& v, float& i, float& spre)
{
    const float sg = sigmoid_fast(v);
    v = v + dt * (mu1 * (i - v) + mu1 * cin);
    i = i + dt * (nmu2 * i);
    spre = spre + dt * sg;
}

// B3a: simulate chunk -> per-chunk sigma sum only (no output traffic).
__global__ void snn_B3a(const float* __restrict__ ts, const float* __restrict__ inp,
                        const float* __restrict__ mu, int T, int N)
{
    const int n = blockIdx.x * blockDim.x + threadIdx.x;
    const int c = blockIdx.y;
    const int t0 = g_tstart;
    const int tb = t0 + c * CHUNK;
    if (n >= N || tb >= T) return;
    const int te = (tb + CHUNK < T) ? tb + CHUNK : T;

    const float dt   = ts[1] - ts[0];
    const float mu1  = mu[0];
    const float nmu2 = -mu[1];

    float v = g_vstart[c * NMAX + n];
    float i = g_istart[c * NMAX + n];
    float spre = 0.0f;

    int t = tb;
    for (; t + 4 <= te; t += 4) {
        const float x0 = inp[(size_t)(t + 0) * N + n];
        const float x1 = inp[(size_t)(t + 1) * N + n];
        const float x2 = inp[(size_t)(t + 2) * N + n];
        const float x3 = inp[(size_t)(t + 3) * N + n];
        stepF(dt, mu1, nmu2, x0, v, i, spre);
        stepF(dt, mu1, nmu2, x1, v, i, spre);
        stepF(dt, mu1, nmu2, x2, v, i, spre);
        stepF(dt, mu1, nmu2, x3, v, i, spre);
    }
    for (; t < te; ++t)
        stepF(dt, mu1, nmu2, inp[(size_t)t * N + n], v, i, spre);

    g_ssum[c * NMAX + n] = spre;
}

// B4: per-neuron scan of chunk sigma-sums -> chunk-start s.
__global__ void snn_B4(int T, int N)
{
    const int n = blockIdx.x * blockDim.x + threadIdx.x;
    if (n >= N) return;
    const int t0 = g_tstart;
    if (t0 >= T) return;
    const int NC = (T - t0 + CHUNK - 1) / CHUNK;

    float s = g_ss[n];
    for (int c = 0; c < NC; ++c) {
        g_sstart[c * NMAX + n] = s;
        s += g_ssum[c * NMAX + n];
    }
}

// B3b: re-simulate each chunk, write (v,i,s) as contiguous 12B records.
__global__ void snn_B3b(const float* __restrict__ ts, const float* __restrict__ inp,
                        const float* __restrict__ mu, float* __restrict__ out,
                        int T, int N)
{
    const int n = blockIdx.x * blockDim.x + threadIdx.x;
    const int c = blockIdx.y;
    const int t0 = g_tstart;
    const int tb = t0 + c * CHUNK;
    if (n >= N || tb >= T) return;
    const int te = (tb + CHUNK < T) ? tb + CHUNK : T;

    const float dt   = ts[1] - ts[0];
    const float mu1  = mu[0];
    const float nmu2 = -mu[1];

    float v = g_vstart[c * NMAX + n];
    float i = g_istart[c * NMAX + n];
    const float sstart = g_sstart[c * NMAX + n];
    float spre = 0.0f;

    int t = tb;
    for (; t + 4 <= te; t += 4) {
        const float x0 = inp[(size_t)(t + 0) * N + n];
        const float x1 = inp[(size_t)(t + 1) * N + n];
        const float x2 = inp[(size_t)(t + 2) * N + n];
        const float x3 = inp[(size_t)(t + 3) * N + n];

        stepF(dt, mu1, nmu2, x0, v, i, spre);
        float* op0 = out + ((size_t)(t + 0) * N + n) * 3;
        op0[0] = v; op0[1] = i; op0[2] = sstart + spre;

        stepF(dt, mu1, nmu2, x1, v, i, spre);
        float* op1 = out + ((size_t)(t + 1) * N + n) * 3;
        op1[0] = v; op1[1] = i; op1[2] = sstart + spre;

        stepF(dt, mu1, nmu2, x2, v, i, spre);
        float* op2 = out + ((size_t)(t + 2) * N + n) * 3;
        op2[0] = v; op2[1] = i; op2[2] = sstart + spre;

        stepF(dt, mu1, nmu2, x3, v, i, spre);
        float* op3 = out + ((size_t)(t + 3) * N + n) * 3;
        op3[0] = v; op3[1] = i; op3[2] = sstart + spre;
    }
    for (; t < te; ++t) {
        stepF(dt, mu1, nmu2, inp[(size_t)t * N + n], v, i, spre);
        float* op = out + ((size_t)t * N + n) * 3;
        op[0] = v; op[1] = i; op[2] = sstart + spre;
    }
}

// ---------------------------------------------------------------------------
extern "C" void kernel_launch(void* const* d_in, const int* in_sizes, int n_in,
                              void* d_out, int out_size)
{
    const float* ts  = (const float*)d_in[0];
    const float* inp = (const float*)d_in[1];
    const float* w   = (const float*)d_in[2];
    const float* v0  = (const float*)d_in[3];
    const float* i0  = (const float*)d_in[4];
    const float* mu  = (const float*)d_in[5];
    const float* s0u = (const float*)d_in[6];
    const float* ru  = (const float*)d_in[7];
    const int*   msp = (const int*)d_in[8];
    float* out = (float*)d_out;

    const int T = in_sizes[0];
    const int N = in_sizes[3];

    snn_phaseA<<<CTAS, THRA>>>(ts, inp, w, v0, i0, mu, s0u, ru, msp, out, T, N);

    dim3 gB((N + 255) / 256, NCMAX);
    snn_B1 <<<gB, 256>>>(ts, inp, mu, T, N);
    snn_B2 <<<(N + 255) / 256, 256>>>(ts, mu, T, N);
    snn_B3a<<<gB, 256>>>(ts, inp, mu, T, N);
    snn_B4 <<<(N + 255) / 256, 256>>>(T, N);
    snn_B3b<<<gB, 256>>>(ts, inp, mu, out, T, N);
}

// round 10
// speedup vs baseline: 2.9237x; 1.0139x over previous
#include <cuda_runtime.h>
#include <cstdint>

// Dataset-fixed shapes: T=2048, N=4096, max_spikes=128.
#define NMAX   4096
#define TMAX   2048
#define CTAS   8
#define THRA   (NMAX / CTAS)      // 512 threads per phase-A CTA, 1 neuron/thread
#define CHUNK  32
#define NCMAX  (TMAX / CHUNK)     // 64 (covers worst case t0 = 0)
#define IDXINF 0x7FFFFFFFu

// Persistent state between phases (static device globals: no allocation).
static __device__ float g_sv[NMAX];
static __device__ float g_si[NMAX];
static __device__ float g_ss[NMAX];
static __device__ int   g_tstart;

// Phase-B scan scratch.
static __device__ float g_P[NCMAX * NMAX];
static __device__ float g_vstart[NCMAX * NMAX];
static __device__ float g_istart[NCMAX * NMAX];
static __device__ float g_ssum[NCMAX * NMAX];
static __device__ float g_sstart[NCMAX * NMAX];

__device__ __forceinline__ float sigmoid_acc(float x) {
    float e = expf(-x);
    float d = __fadd_rn(1.0f, e);
    return 1.0f / d;     // accurate: matches reference to ~1-2 ulp (validated)
}
__device__ __forceinline__ float sigmoid_fast(float x) {
    return __fdividef(1.0f, 1.0f + __expf(-x));   // phase B only (no thresholds)
}

__device__ __forceinline__ uint32_t smem_u32(const void* p) {
    uint32_t a;
    asm("{ .reg .u64 t; cvta.to.shared.u64 t, %1; cvt.u32.u64 %0, t; }"
        : "=r"(a) : "l"(p));
    return a;
}

__device__ __forceinline__ uint32_t mapa_u32(uint32_t local_addr, unsigned rank) {
    uint32_t remote;
    asm("mapa.shared::cluster.u32 %0, %1, %2;"
        : "=r"(remote) : "r"(local_addr), "r"(rank));
    return remote;
}

__device__ __forceinline__ void mbar_arrive_expect_tx(uint32_t mbar, unsigned tx) {
    asm volatile("mbarrier.arrive.expect_tx.shared.b64 _, [%0], %1;"
                 :: "r"(mbar), "r"(tx) : "memory");
}

// Push 4B into a peer CTA's smem slot and signal its mbarrier (tx += 4).
__device__ __forceinline__ void st_async_u32(uint32_t raddr, unsigned val, uint32_t rmbar) {
    asm volatile("st.async.shared::cluster.mbarrier::complete_tx::bytes.b32 [%0], %1, [%2];"
                 :: "r"(raddr), "r"(val), "r"(rmbar) : "memory");
}

// Hint-less busy poll: NO suspend-time hint. The 10ms-hint variant parks the
// warp and pays us-scale wakeup per step (prime suspect for 1.7us/step).
__device__ __forceinline__ void mbar_wait_parity_cluster(uint32_t mbar, unsigned parity) {
    unsigned done;
    do {
        asm volatile(
            "{\n\t.reg .pred p;\n\t"
            "mbarrier.try_wait.parity.acquire.cluster.shared::cta.b64 p, [%1], %2;\n\t"
            "selp.b32 %0, 1, 0, p;\n\t}"
            : "=r"(done) : "r"(mbar), "r"(parity) : "memory");
    } while (!done);
}

// No-op kernel: 5 of these are launched before snn_phaseA so that ncu's
// fixed "-s 5 -c 1" capture window lands on snn_phaseA next round.
__global__ void snn_nop() {}

// ---------------------------------------------------------------------------
// Phase A: coupled event phase. 8-CTA cluster, 1 neuron/thread.
// Structure identical to the R4/R9-passing kernel except:
//   (1) mbarrier wait is a hint-less spin (above),
//   (2) sjump/logf is computed only for crossing lanes (value identical when
//       consumed -> float sequence unchanged).
// Exact-rounding ops in the reference's expression order.
// ---------------------------------------------------------------------------
__global__ void __cluster_dims__(CTAS, 1, 1) __launch_bounds__(THRA, 1)
snn_phaseA(const float* __restrict__ ts, const float* __restrict__ inp,
           const float* __restrict__ w, const float* __restrict__ v0,
           const float* __restrict__ i0, const float* __restrict__ mu,
           const float* __restrict__ s0u, const float* __restrict__ ru,
           const int* __restrict__ msp, float* __restrict__ out,
           int T, int N)
{
    __shared__ unsigned sh_warpmin[THRA / 32];
    __shared__ unsigned sh_slots[2][CTAS];              // [parity][src_rank]
    __shared__ alignas(8) unsigned long long sh_mbar;

    unsigned rank;
    asm("mov.u32 %0, %%cluster_ctarank;" : "=r"(rank));

    const int tid  = threadIdx.x;
    const int lane = tid & 31;
    const int wid  = tid >> 5;
    const int n    = (int)rank * THRA + tid;

    const float dt   = __fsub_rn(ts[1], ts[0]);
    const float mu1  = mu[0];
    const float nmu2 = -mu[1];
    const int max_spikes = msp[0];

    const uint32_t slots_addr = smem_u32(sh_slots);
    const uint32_t mbar_addr  = smem_u32((const void*)&sh_mbar);

    if (tid == 0) {
        asm volatile("mbarrier.init.shared.b64 [%0], %1;"
                     :: "r"(mbar_addr), "r"(1u) : "memory");
    }
    __syncthreads();
    asm volatile("barrier.cluster.arrive.aligned;" ::: "memory");
    asm volatile("barrier.cluster.wait.aligned;" ::: "memory");

    float v    = v0[n];                  // final v of previous step
    float iPre = i0[n];                  // i of previous step, w-add may be pending
    float s    = __fsub_rn(logf(__fadd_rn(s0u[n], 1e-12f)), 0.01f);
    bool  pend = false;
    float wv   = 0.0f;
    float cin  = inp[n];                 // inp row t = 0

    int nsp = 0;
    int t_end = T;

    for (int t = 0; t < T; ++t) {
        // Early independent loads (latency hidden across the step).
        const float ruv = ru[(size_t)t * N + n];
        const int   tn  = (t + 1 < T) ? t + 1 : T - 1;
        const float nin = inp[(size_t)tn * N + n];

        // Threshold state first — it feeds the inter-CTA reduction.
        const float sg   = sigmoid_acc(v);                    // sigmoid of OLD v
        const float sn0  = __fadd_rn(s, __fmul_rn(dt, sg));
        const bool  cross = (sn0 >= 0.0f);

        unsigned lm = cross ? (unsigned)n : IDXINF;
        lm = __reduce_min_sync(0xFFFFFFFFu, lm);
        if (lane == 0) sh_warpmin[wid] = lm;
        __syncthreads();
        if (wid == 0) {
            unsigned m = (lane < THRA / 32) ? sh_warpmin[lane] : IDXINF;
            m = __reduce_min_sync(0xFFFFFFFFu, m);
            if (lane == 0) mbar_arrive_expect_tx(mbar_addr, 4u * CTAS);
            if (lane < CTAS) {
                const uint32_t la = slots_addr + ((unsigned)(t & 1) * CTAS + rank) * 4u;
                st_async_u32(mapa_u32(la, (unsigned)lane), m,
                             mapa_u32(mbar_addr, (unsigned)lane));
            }
        }

        // ---- deferred finalization of step t-1 (off the sync critical path) ----
        const float ifin = pend ? __fadd_rn(iPre, wv) : iPre;
        if (t > 0) {
            float* op = out + ((size_t)(t - 1) * N + n) * 3;
            op[0] = v; op[1] = ifin; op[2] = s;
        }

        // Pre-fire values for step t.
        const float d1 = __fsub_rn(ifin, v);
        const float va = __fmul_rn(mu1, d1);
        const float vb = __fmul_rn(mu1, cin);
        float vn = __fadd_rn(v, __fmul_rn(dt, __fadd_rn(va, vb)));
        float in = __fadd_rn(ifin, __fmul_rn(dt, __fmul_rn(nmu2, ifin)));
        float sn = sn0;
        // Resample value: only crossing lanes ever consume it.
        float sjump = 0.0f;
        if (cross)
            sjump = __fsub_rn(logf(__fadd_rn(ruv, 1e-12f)), 0.01f);

        // Wait for all 8 candidates, gather from local smem.
        mbar_wait_parity_cluster(mbar_addr, (unsigned)(t & 1));
        unsigned idx = sh_slots[t & 1][0];
        #pragma unroll
        for (int r = 1; r < CTAS; ++r) idx = min(idx, sh_slots[t & 1][r]);

        const bool fire = (idx != IDXINF) && (nsp < max_spikes);
        pend = false;
        if (fire) {
            if (cross) {
                vn = __fsub_rn(vn, 1.0f);          // V_RESET
                sn = sjump;
            } else {
                pend = true;
                wv = w[(size_t)idx * N + n];       // DRAM load, ~1 step of slack
            }
            ++nsp;
        }

        v = vn; iPre = in; s = sn; cin = nin;
        if (nsp >= max_spikes) { t_end = t + 1; break; }    // cluster-uniform
    }

    // Epilogue: finalize and store the last computed row.
    const float ifin = pend ? __fadd_rn(iPre, wv) : iPre;
    {
        float* op = out + ((size_t)(t_end - 1) * N + n) * 3;
        op[0] = v; op[1] = ifin; op[2] = s;
    }
    g_sv[n] = v; g_si[n] = ifin; g_ss[n] = s;
    if (rank == 0 && tid == 0) g_tstart = t_end;
}

// ---------------------------------------------------------------------------
// Phase B (fire permanently false): blocked parallel scan over t.
//   v' = a*v + b*(i + inp_t);  i' = r*i;  s' = s + dt*sigmoid(v)
// Identical to the R9-passing kernels.
// ---------------------------------------------------------------------------

// B1: per (chunk, neuron) input response P (v evolved from v=0, i=0).
__global__ void snn_B1(const float* __restrict__ ts, const float* __restrict__ inp,
                       const float* __restrict__ mu, int T, int N)
{
    const int n = blockIdx.x * blockDim.x + threadIdx.x;
    const int c = blockIdx.y;
    const int t0 = g_tstart;
    const int tb = t0 + c * CHUNK;
    if (n >= N || tb >= T) return;
    const int te = (tb + CHUNK < T) ? tb + CHUNK : T;

    const float dt = ts[1] - ts[0];
    const float a  = 1.0f - dt * mu[0];
    const float b  = dt * mu[0];

    float P = 0.0f;
    int t = tb;
    for (; t + 4 <= te; t += 4) {
        const float x0 = inp[(size_t)(t + 0) * N + n];
        const float x1 = inp[(size_t)(t + 1) * N + n];
        const float x2 = inp[(size_t)(t + 2) * N + n];
        const float x3 = inp[(size_t)(t + 3) * N + n];
        P = __fmaf_rn(a, P, b * x0);
        P = __fmaf_rn(a, P, b * x1);
        P = __fmaf_rn(a, P, b * x2);
        P = __fmaf_rn(a, P, b * x3);
    }
    for (; t < te; ++t)
        P = __fmaf_rn(a, P, b * inp[(size_t)t * N + n]);
    g_P[c * NMAX + n] = P;
}

// B2: per-neuron combine over chunks -> chunk-start (v, i).
__global__ void snn_B2(const float* __restrict__ ts, const float* __restrict__ mu,
                       int T, int N)
{
    const int n = blockIdx.x * blockDim.x + threadIdx.x;
    if (n >= N) return;
    const int t0 = g_tstart;
    if (t0 >= T) return;
    const int NC = (T - t0 + CHUNK - 1) / CHUNK;

    const float dt = ts[1] - ts[0];
    const float a  = 1.0f - dt * mu[0];
    const float b  = dt * mu[0];
    const float r  = 1.0f - dt * mu[1];

    // Full-chunk composed scalars: v_end = A*v0 + Q*i0 + P, i_end = R*i0.
    float A = 1.0f, Q = 0.0f, R = 1.0f;
    #pragma unroll 8
    for (int j = 0; j < CHUNK; ++j) { Q = a * Q + b * R; A *= a; R *= r; }

    float v = g_sv[n];
    float i = g_si[n];
    for (int c = 0; c < NC; ++c) {
        g_vstart[c * NMAX + n] = v;
        g_istart[c * NMAX + n] = i;
        if (c < NC - 1) {
            const float vn = A * v + Q * i + g_P[c * NMAX + n];
            i = R * i;
            v = vn;
        }
    }
}

// One fast step (sigmoid of OLD v); phase B only.
__device__ __forceinline__ void stepF(float dt, float mu1, float nmu2, float cin,
                                      float& v, float& i, float& spre)
{
    const float sg = sigmoid_fast(v);
    v = v + dt * (mu1 * (i - v) + mu1 * cin);
    i = i + dt * (nmu2 * i);
    spre = spre + dt * sg;
}

// B3a: simulate chunk -> per-chunk sigma sum only (no output traffic).
__global__ void snn_B3a(const float* __restrict__ ts, const float* __restrict__ inp,
                        const float* __restrict__ mu, int T, int N)
{
    const int n = blockIdx.x * blockDim.x + threadIdx.x;
    const int c = blockIdx.y;
    const int t0 = g_tstart;
    const int tb = t0 + c * CHUNK;
    if (n >= N || tb >= T) return;
    const int te = (tb + CHUNK < T) ? tb + CHUNK : T;

    const float dt   = ts[1] - ts[0];
    const float mu1  = mu[0];
    const float nmu2 = -mu[1];

    float v = g_vstart[c * NMAX + n];
    float i = g_istart[c * NMAX + n];
    float spre = 0.0f;

    int t = tb;
    for (; t + 4 <= te; t += 4) {
        const float x0 = inp[(size_t)(t + 0) * N + n];
        const float x1 = inp[(size_t)(t + 1) * N + n];
        const float x2 = inp[(size_t)(t + 2) * N + n];
        const float x3 = inp[(size_t)(t + 3) * N + n];
        stepF(dt, mu1, nmu2, x0, v, i, spre);
        stepF(dt, mu1, nmu2, x1, v, i, spre);
        stepF(dt, mu1, nmu2, x2, v, i, spre);
        stepF(dt, mu1, nmu2, x3, v, i, spre);
    }
    for (; t < te; ++t)
        stepF(dt, mu1, nmu2, inp[(size_t)t * N + n], v, i, spre);

    g_ssum[c * NMAX + n] = spre;
}

// B4: per-neuron scan of chunk sigma-sums -> chunk-start s.
__global__ void snn_B4(int T, int N)
{
    const int n = blockIdx.x * blockDim.x + threadIdx.x;
    if (n >= N) return;
    const int t0 = g_tstart;
    if (t0 >= T) return;
    const int NC = (T - t0 + CHUNK - 1) / CHUNK;

    float s = g_ss[n];
    for (int c = 0; c < NC; ++c) {
        g_sstart[c * NMAX + n] = s;
        s += g_ssum[c * NMAX + n];
    }
}

// B3b: re-simulate each chunk, write (v,i,s) as contiguous 12B records.
__global__ void snn_B3b(const float* __restrict__ ts, const float* __restrict__ inp,
                        const float* __restrict__ mu, float* __restrict__ out,
                        int T, int N)
{
    const int n = blockIdx.x * blockDim.x + threadIdx.x;
    const int c = blockIdx.y;
    const int t0 = g_tstart;
    const int tb = t0 + c * CHUNK;
    if (n >= N || tb >= T) return;
    const int te = (tb + CHUNK < T) ? tb + CHUNK : T;

    const float dt   = ts[1] - ts[0];
    const float mu1  = mu[0];
    const float nmu2 = -mu[1];

    float v = g_vstart[c * NMAX + n];
    float i = g_istart[c * NMAX + n];
    const float sstart = g_sstart[c * NMAX + n];
    float spre = 0.0f;

    int t = tb;
    for (; t + 4 <= te; t += 4) {
        const float x0 = inp[(size_t)(t + 0) * N + n];
        const float x1 = inp[(size_t)(t + 1) * N + n];
        const float x2 = inp[(size_t)(t + 2) * N + n];
        const float x3 = inp[(size_t)(t + 3) * N + n];

        stepF(dt, mu1, nmu2, x0, v, i, spre);
        float* op0 = out + ((size_t)(t + 0) * N + n) * 3;
        op0[0] = v; op0[1] = i; op0[2] = sstart + spre;

        stepF(dt, mu1, nmu2, x1, v, i, spre);
        float* op1 = out + ((size_t)(t + 1) * N + n) * 3;
        op1[0] = v; op1[1] = i; op1[2] = sstart + spre;

        stepF(dt, mu1, nmu2, x2, v, i, spre);
        float* op2 = out + ((size_t)(t + 2) * N + n) * 3;
        op2[0] = v; op2[1] = i; op2[2] = sstart + spre;

        stepF(dt, mu1, nmu2, x3, v, i, spre);
        float* op3 = out + ((size_t)(t + 3) * N + n) * 3;
        op3[0] = v; op3[1] = i; op3[2] = sstart + spre;
    }
    for (; t < te; ++t) {
        stepF(dt, mu1, nmu2, inp[(size_t)t * N + n], v, i, spre);
        float* op = out + ((size_t)t * N + n) * 3;
        op[0] = v; op[1] = i; op[2] = sstart + spre;
    }
}

// ---------------------------------------------------------------------------
extern "C" void kernel_launch(void* const* d_in, const int* in_sizes, int n_in,
                              void* d_out, int out_size)
{
    const float* ts  = (const float*)d_in[0];
    const float* inp = (const float*)d_in[1];
    const float* w   = (const float*)d_in[2];
    const float* v0  = (const float*)d_in[3];
    const float* i0  = (const float*)d_in[4];
    const float* mu  = (const float*)d_in[5];
    const float* s0u = (const float*)d_in[6];
    const float* ru  = (const float*)d_in[7];
    const int*   msp = (const int*)d_in[8];
    float* out = (float*)d_out;

    const int T = in_sizes[0];
    const int N = in_sizes[3];

    // 5 no-ops so ncu's "-s 5 -c 1" window captures snn_phaseA (launch #6).
    snn_nop<<<1, 32>>>(); snn_nop<<<1, 32>>>(); snn_nop<<<1, 32>>>();
    snn_nop<<<1, 32>>>(); snn_nop<<<1, 32>>>();

    snn_phaseA<<<CTAS, THRA>>>(ts, inp, w, v0, i0, mu, s0u, ru, msp, out, T, N);

    dim3 gB((N + 255) / 256, NCMAX);
    snn_B1 <<<gB, 256>>>(ts, inp, mu, T, N);
    snn_B2 <<<(N + 255) / 256, 256>>>(ts, mu, T, N);
    snn_B3a<<<gB, 256>>>(ts, inp, mu, T, N);
    snn_B4 <<<(N + 255) / 256, 256>>>(T, N);
    snn_B3b<<<gB, 256>>>(ts, inp, mu, out, T, N);
}